// round 7
// baseline (speedup 1.0000x reference)
#include <cuda_runtime.h>
#include <cstdint>

// ---------------- problem constants ----------------
#define Nn     30000
#define F_IN   128
#define F_H    256
#define NHEAD  8
#define CCH    32
#define NEG_SLOPE 0.2f
#define SCAN_T 1024
#define CHUNK  30          // ceil(30000/1024)
#define EMAX   480000

// ---------------- device scratch (no allocs allowed) ----------------
__device__ float g_h  [(size_t)Nn * F_H];
__device__ float g_x2 [(size_t)Nn * F_H];
__device__ float g_as [(size_t)Nn * NHEAD];
__device__ float g_ad [(size_t)Nn * NHEAD];
__device__ float g_wT [(size_t)NHEAD * EMAX];   // head-major edge weights
__device__ int   g_count [Nn];
__device__ int   g_rowptr[Nn + 1];
__device__ int   g_cursor[Nn];
__device__ int   g_csrc  [EMAX + 1024];         // src list grouped by dst

__device__ __forceinline__ float leaky(float v) {
    return (v > 0.f) ? v : NEG_SLOPE * v;
}
__device__ __forceinline__ unsigned f2tf32(float f) {
    unsigned u;
    asm("cvt.rna.tf32.f32 %0, %1;" : "=r"(u) : "f"(f));
    return u;
}
__device__ __forceinline__ void mma_tf32(float c[4], const unsigned a[4], const unsigned b[2]) {
    asm volatile(
        "mma.sync.aligned.m16n8k8.row.col.f32.tf32.tf32.f32 "
        "{%0,%1,%2,%3}, {%4,%5,%6,%7}, {%8,%9}, {%0,%1,%2,%3};"
        : "+f"(c[0]), "+f"(c[1]), "+f"(c[2]), "+f"(c[3])
        : "r"(a[0]), "r"(a[1]), "r"(a[2]), "r"(a[3]), "r"(b[0]), "r"(b[1]));
}

// ---------------- tf32 MMA GEMM with register double-buffering ----------------
#define AP 20
#define BP 136

template <int K>
__global__ void __launch_bounds__(256) k_gemm_tf32(const float* __restrict__ A,
                                                   const float* __restrict__ W,
                                                   float* __restrict__ Cout) {
    __shared__ unsigned As[128 * AP];
    __shared__ unsigned Bs[16 * BP];

    const int tid    = threadIdx.x;
    const int lane   = tid & 31;
    const int warpid = tid >> 5;
    const int row0   = blockIdx.y * 128;
    const int col0   = blockIdx.x * 128;
    const int wm     = (warpid & 3) * 32;
    const int wn     = (warpid >> 2) * 64;
    const int lg     = lane >> 2;
    const int lt     = lane & 3;

    float c[2][8][4];
#pragma unroll
    for (int t = 0; t < 2; t++)
#pragma unroll
        for (int j = 0; j < 8; j++)
#pragma unroll
            for (int r = 0; r < 4; r++) c[t][j][r] = 0.f;

    const int  a_row = tid >> 1;
    const int  a_c0  = (tid & 1) * 8;
    const int  b_k   = tid >> 4;
    const int  b_n0  = (tid & 15) * 4;
    const bool a_ok  = (row0 + a_row) < Nn;

    float4 a_reg[2], b_reg[2];
    // prologue: load tile k0=0 into registers
#pragma unroll
    for (int i = 0; i < 2; i++) {
        a_reg[i] = make_float4(0.f, 0.f, 0.f, 0.f);
        if (a_ok)
            a_reg[i] = *(const float4*)(A + (size_t)(row0 + a_row) * K + a_c0 + i * 4);
        b_reg[i] = *(const float4*)(W + (size_t)b_k * F_H + col0 + b_n0 + i * 64);
    }

    for (int k0 = 0; k0 < K; k0 += 16) {
        // convert + store the staged registers
#pragma unroll
        for (int i = 0; i < 2; i++) {
            float4 v = a_reg[i];
            *(uint4*)&As[a_row * AP + a_c0 + i * 4] =
                make_uint4(f2tf32(v.x), f2tf32(v.y), f2tf32(v.z), f2tf32(v.w));
            v = b_reg[i];
            *(uint4*)&Bs[b_k * BP + b_n0 + i * 64] =
                make_uint4(f2tf32(v.x), f2tf32(v.y), f2tf32(v.z), f2tf32(v.w));
        }
        __syncthreads();

        // issue next tile's global loads (latency hidden behind MMA below)
        if (k0 + 16 < K) {
#pragma unroll
            for (int i = 0; i < 2; i++) {
                a_reg[i] = make_float4(0.f, 0.f, 0.f, 0.f);
                if (a_ok)
                    a_reg[i] = *(const float4*)(A + (size_t)(row0 + a_row) * K + k0 + 16 + a_c0 + i * 4);
                b_reg[i] = *(const float4*)(W + (size_t)(k0 + 16 + b_k) * F_H + col0 + b_n0 + i * 64);
            }
        }

#pragma unroll
        for (int kk = 0; kk < 16; kk += 8) {
            unsigned a[2][4];
#pragma unroll
            for (int t = 0; t < 2; t++) {
                int mr = wm + t * 16;
                a[t][0] = As[(mr + lg) * AP + kk + lt];
                a[t][1] = As[(mr + lg + 8) * AP + kk + lt];
                a[t][2] = As[(mr + lg) * AP + kk + lt + 4];
                a[t][3] = As[(mr + lg + 8) * AP + kk + lt + 4];
            }
#pragma unroll
            for (int j = 0; j < 8; j++) {
                unsigned b[2];
                int n = wn + j * 8 + lg;
                b[0] = Bs[(kk + lt) * BP + n];
                b[1] = Bs[(kk + lt + 4) * BP + n];
                mma_tf32(c[0][j], a[0], b);
                mma_tf32(c[1][j], a[1], b);
            }
        }
        __syncthreads();
    }

#pragma unroll
    for (int t = 0; t < 2; t++) {
        int r0 = row0 + wm + t * 16 + lg;
#pragma unroll
        for (int j = 0; j < 8; j++) {
            int cc = col0 + wn + j * 8 + lt * 2;
            if (r0 < Nn)
                *(float2*)(Cout + (size_t)r0 * F_H + cc) = make_float2(c[t][j][0], c[t][j][1]);
            if (r0 + 8 < Nn)
                *(float2*)(Cout + (size_t)(r0 + 8) * F_H + cc) = make_float2(c[t][j][2], c[t][j][3]);
        }
    }
}

// ---------------- alpha projections ----------------
__global__ void k_alpha(const float* __restrict__ a_src, const float* __restrict__ a_dst) {
    int idx = blockIdx.x * blockDim.x + threadIdx.x;
    if (idx >= Nn * NHEAD) return;
    int n = idx >> 3, h = idx & 7;
    const float4* hp = (const float4*)(g_h + (size_t)n * F_H + h * CCH);
    const float4* as = (const float4*)(a_src + h * CCH);
    const float4* ad = (const float4*)(a_dst + h * CCH);
    float s = 0.f, d = 0.f;
#pragma unroll
    for (int i = 0; i < 8; i++) {
        float4 v = hp[i], a = as[i], b = ad[i];
        s += v.x * a.x + v.y * a.y + v.z * a.z + v.w * a.w;
        d += v.x * b.x + v.y * b.y + v.z * b.z + v.w * b.w;
    }
    g_as[idx] = s;
    g_ad[idx] = d;
}

// ---------------- CSR build ----------------
__global__ void k_zero_count() {
    int i = blockIdx.x * blockDim.x + threadIdx.x;
    if (i < Nn) g_count[i] = 0;
}
__global__ void k_count(const int* __restrict__ ei, int E) {
    int e = blockIdx.x * blockDim.x + threadIdx.x;
    if (e < E) atomicAdd(&g_count[ei[E + e]], 1);
}
__global__ void __launch_bounds__(SCAN_T) k_scan(int E) {
    __shared__ int ssum[SCAN_T];
    int t = threadIdx.x;
    int base = t * CHUNK;
    int s = 0;
#pragma unroll
    for (int i = 0; i < CHUNK; i++) {
        int idx = base + i;
        if (idx < Nn) s += g_count[idx];
    }
    ssum[t] = s;
    __syncthreads();
    for (int off = 1; off < SCAN_T; off <<= 1) {
        int v = (t >= off) ? ssum[t - off] : 0;
        __syncthreads();
        ssum[t] += v;
        __syncthreads();
    }
    int run = ssum[t] - s;
#pragma unroll
    for (int i = 0; i < CHUNK; i++) {
        int idx = base + i;
        if (idx < Nn) {
            int c = g_count[idx];
            g_rowptr[idx] = run;
            g_cursor[idx] = run;
            run += c;
        }
    }
    if (t == 0) g_rowptr[Nn] = E;
}
__global__ void k_scatter(const int* __restrict__ ei, int E) {
    int e = blockIdx.x * blockDim.x + threadIdx.x;
    if (e >= E) return;
    int dst = ei[E + e];
    int pos = atomicAdd(&g_cursor[dst], 1);
    g_csrc[pos] = ei[e];
}
// permutation: g_csrc[p] = src of edge; store matching dst-order weights later.
// We need weights in CSR (dst-grouped) order. Compute them directly from g_csrc
// and the node the row belongs to -- but that needs dst per position. Instead
// store dst per position during scatter into g_cdst? Simpler: weight kernel is
// CSR-position-parallel using a per-position dst lookup built once.
__device__ int g_cdst[EMAX + 1024];
__global__ void k_scatter2(const int* __restrict__ ei, int E) {
    int e = blockIdx.x * blockDim.x + threadIdx.x;
    if (e >= E) return;
    int dst = ei[E + e];
    int pos = atomicAdd(&g_cursor[dst], 1);
    g_csrc[pos] = ei[e];
    g_cdst[pos] = dst;
}

// ---------------- edge-parallel weights in CSR order, head-major ----------------
__global__ void k_weights(int E) {
    int e = blockIdx.x * blockDim.x + threadIdx.x;
    if (e >= E) return;
    int src = g_csrc[e];
    int dst = g_cdst[e];
    float4 s0 = *(const float4*)(g_as + src * NHEAD);
    float4 s1 = *(const float4*)(g_as + src * NHEAD + 4);
    float4 d0 = *(const float4*)(g_ad + dst * NHEAD);
    float4 d1 = *(const float4*)(g_ad + dst * NHEAD + 4);
    g_wT[0 * (size_t)E + e] = __expf(leaky(s0.x + d0.x));
    g_wT[1 * (size_t)E + e] = __expf(leaky(s0.y + d0.y));
    g_wT[2 * (size_t)E + e] = __expf(leaky(s0.z + d0.z));
    g_wT[3 * (size_t)E + e] = __expf(leaky(s0.w + d0.w));
    g_wT[4 * (size_t)E + e] = __expf(leaky(s1.x + d1.x));
    g_wT[5 * (size_t)E + e] = __expf(leaky(s1.y + d1.y));
    g_wT[6 * (size_t)E + e] = __expf(leaky(s1.z + d1.z));
    g_wT[7 * (size_t)E + e] = __expf(leaky(s1.w + d1.w));
}

// ---------------- streaming pull aggregation ----------------
// Block = node, warp = head, lane = channel. No smem phases, no scalar
// random loads: indices + weights loaded coalesced, distributed via shfl.
template <bool FINAL>
__global__ void __launch_bounds__(256) k_agg(int E,
                                             const float* __restrict__ b,
                                             const float* __restrict__ Wl,
                                             const float* __restrict__ bl,
                                             float* __restrict__ out) {
    __shared__ float part[NHEAD];

    const int n    = blockIdx.x;
    const int tid  = threadIdx.x;
    const int wid  = tid >> 5, lane = tid & 31;
    const int f    = wid * CCH + lane;
    const int beg  = g_rowptr[n], end = g_rowptr[n + 1];
    const float* __restrict__ wrow = g_wT + (size_t)wid * E;

    const float ws = __expf(leaky(g_as[n * NHEAD + wid] + g_ad[n * NHEAD + wid]));
    float den = ws;
    float acc = ws * g_h[(size_t)n * F_H + f];

    for (int base = beg; base < end; base += 32) {
        const int m = end - base;                 // >=1
        int   sidx = 0;
        float wv   = 0.f;
        if (lane < m) {
            sidx = g_csrc[base + lane];
            wv   = wrow[base + lane];
        }
        const int cnt = (m < 32) ? m : 32;
        int g = 0;
        for (; g + 8 <= cnt; g += 8) {
            int   s[8]; float w[8], hv[8];
#pragma unroll
            for (int i = 0; i < 8; i++) s[i] = __shfl_sync(0xFFFFFFFFu, sidx, g + i);
#pragma unroll
            for (int i = 0; i < 8; i++) w[i] = __shfl_sync(0xFFFFFFFFu, wv, g + i);
#pragma unroll
            for (int i = 0; i < 8; i++) hv[i] = __ldg(&g_h[(size_t)s[i] * F_H + f]);
#pragma unroll
            for (int i = 0; i < 8; i++) { den += w[i]; acc += w[i] * hv[i]; }
        }
        if (g < cnt) {                            // branch-free masked 8-wide tail
            int   s[8]; float w[8], hv[8];
#pragma unroll
            for (int i = 0; i < 8; i++) {
                int t = g + i;
                int tt = (t < 32) ? t : 0;
                s[i] = __shfl_sync(0xFFFFFFFFu, sidx, tt);
                float ww = __shfl_sync(0xFFFFFFFFu, wv, tt);
                w[i] = (t < cnt) ? ww : 0.f;      // wv already 0 for lanes >= m
            }
#pragma unroll
            for (int i = 0; i < 8; i++) hv[i] = __ldg(&g_h[(size_t)s[i] * F_H + f]);
#pragma unroll
            for (int i = 0; i < 8; i++) { den += w[i]; acc += w[i] * hv[i]; }
        }
    }

    float v = acc / den + b[f];
    v = (v > 0.f) ? v : expm1f(v);

    if (!FINAL) {
        g_x2[(size_t)n * F_H + f] = v;
    } else {
        float p = v * Wl[f];
#pragma unroll
        for (int o = 16; o > 0; o >>= 1) p += __shfl_down_sync(0xFFFFFFFFu, p, o);
        if (lane == 0) part[wid] = p;
        __syncthreads();
        if (tid == 0) {
            float s = bl[0];
#pragma unroll
            for (int i = 0; i < NHEAD; i++) s += part[i];
            out[n] = s;
        }
    }
}

// ---------------- host ----------------
extern "C" void kernel_launch(void* const* d_in, const int* in_sizes, int n_in,
                              void* d_out, int out_size) {
    const float* x   = (const float*)d_in[0];
    const int*   ei  = (const int*)  d_in[1];
    const float* W1  = (const float*)d_in[2];
    const float* a1s = (const float*)d_in[3];
    const float* a1d = (const float*)d_in[4];
    const float* b1  = (const float*)d_in[5];
    const float* W2  = (const float*)d_in[6];
    const float* a2s = (const float*)d_in[7];
    const float* a2d = (const float*)d_in[8];
    const float* b2  = (const float*)d_in[9];
    const float* Wl  = (const float*)d_in[10];
    const float* bl  = (const float*)d_in[11];
    float* out = (float*)d_out;

    const int E = in_sizes[1] / 2;          // 480000

    float* g_h_p;  cudaGetSymbolAddress((void**)&g_h_p,  g_h);
    float* g_x2_p; cudaGetSymbolAddress((void**)&g_x2_p, g_x2);

    const int T = 256;
    dim3 gemm_grid(F_H / 128, (Nn + 127) / 128);
    int nh_blocks = (Nn * NHEAD + T - 1) / T;
    int e_blocks  = (E + T - 1) / T;

    // ---------- CSR build (shared by both layers) ----------
    k_zero_count<<<(Nn + T - 1) / T, T>>>();
    k_count<<<e_blocks, T>>>(ei, E);
    k_scan<<<1, SCAN_T>>>(E);
    k_scatter2<<<e_blocks, T>>>(ei, E);

    // ---------- layer 1 ----------
    k_gemm_tf32<F_IN><<<gemm_grid, T>>>(x, W1, g_h_p);
    k_alpha<<<nh_blocks, T>>>(a1s, a1d);
    k_weights<<<e_blocks, T>>>(E);
    k_agg<false><<<Nn, T>>>(E, b1, nullptr, nullptr, nullptr);

    // ---------- layer 2 ----------
    k_gemm_tf32<F_H><<<gemm_grid, T>>>(g_x2_p, W2, g_h_p);
    k_alpha<<<nh_blocks, T>>>(a2s, a2d);
    k_weights<<<e_blocks, T>>>(E);
    k_agg<true><<<Nn, T>>>(E, b2, Wl, bl, out);
}

// round 9
// speedup vs baseline: 1.0605x; 1.0605x over previous
#include <cuda_runtime.h>
#include <cstdint>

// ---------------- problem constants ----------------
#define Nn     30000
#define F_IN   128
#define F_H    256
#define NHEAD  8
#define CCH    32
#define NEG_SLOPE 0.2f
#define SCAN_T 1024
#define CHUNK  30          // ceil(30000/1024)
#define EMAX   480000

// ---------------- device scratch (no allocs allowed) ----------------
__device__ float g_h  [(size_t)Nn * F_H];
__device__ float g_agg[(size_t)Nn * F_H];
__device__ float g_x2 [(size_t)Nn * F_H];
__device__ float g_as [(size_t)Nn * NHEAD];
__device__ float g_ad [(size_t)Nn * NHEAD];
__device__ float g_den[(size_t)Nn * NHEAD];
__device__ float g_wT [(size_t)NHEAD * EMAX];   // head-major edge weights, CSR order
__device__ int   g_count [Nn];
__device__ int   g_rowptr[Nn + 1];
__device__ int   g_cursor[Nn];
__device__ int   g_csrc  [EMAX + 1024];         // src per CSR position
__device__ int   g_cdst  [EMAX + 1024];         // dst per CSR position

__device__ __forceinline__ void red4(float* p, float a, float b, float c, float d) {
    asm volatile("red.global.add.v4.f32 [%0], {%1,%2,%3,%4};"
                 :: "l"(p), "f"(a), "f"(b), "f"(c), "f"(d) : "memory");
}
__device__ __forceinline__ float leaky(float v) {
    return (v > 0.f) ? v : NEG_SLOPE * v;
}
__device__ __forceinline__ unsigned f2tf32(float f) {
    unsigned u;
    asm("cvt.rna.tf32.f32 %0, %1;" : "=r"(u) : "f"(f));
    return u;
}
__device__ __forceinline__ void mma_tf32(float c[4], const unsigned a[4], const unsigned b[2]) {
    asm volatile(
        "mma.sync.aligned.m16n8k8.row.col.f32.tf32.tf32.f32 "
        "{%0,%1,%2,%3}, {%4,%5,%6,%7}, {%8,%9}, {%0,%1,%2,%3};"
        : "+f"(c[0]), "+f"(c[1]), "+f"(c[2]), "+f"(c[3])
        : "r"(a[0]), "r"(a[1]), "r"(a[2]), "r"(a[3]), "r"(b[0]), "r"(b[1]));
}

// ---------------- tf32 MMA GEMM with register double-buffering ----------------
#define AP 20
#define BP 136

template <int K>
__global__ void __launch_bounds__(256) k_gemm_tf32(const float* __restrict__ A,
                                                   const float* __restrict__ W,
                                                   float* __restrict__ Cout) {
    __shared__ unsigned As[128 * AP];
    __shared__ unsigned Bs[16 * BP];

    const int tid    = threadIdx.x;
    const int lane   = tid & 31;
    const int warpid = tid >> 5;
    const int row0   = blockIdx.y * 128;
    const int col0   = blockIdx.x * 128;
    const int wm     = (warpid & 3) * 32;
    const int wn     = (warpid >> 2) * 64;
    const int lg     = lane >> 2;
    const int lt     = lane & 3;

    float c[2][8][4];
#pragma unroll
    for (int t = 0; t < 2; t++)
#pragma unroll
        for (int j = 0; j < 8; j++)
#pragma unroll
            for (int r = 0; r < 4; r++) c[t][j][r] = 0.f;

    const int  a_row = tid >> 1;
    const int  a_c0  = (tid & 1) * 8;
    const int  b_k   = tid >> 4;
    const int  b_n0  = (tid & 15) * 4;
    const bool a_ok  = (row0 + a_row) < Nn;

    float4 a_reg[2], b_reg[2];
#pragma unroll
    for (int i = 0; i < 2; i++) {
        a_reg[i] = make_float4(0.f, 0.f, 0.f, 0.f);
        if (a_ok)
            a_reg[i] = *(const float4*)(A + (size_t)(row0 + a_row) * K + a_c0 + i * 4);
        b_reg[i] = *(const float4*)(W + (size_t)b_k * F_H + col0 + b_n0 + i * 64);
    }

    for (int k0 = 0; k0 < K; k0 += 16) {
#pragma unroll
        for (int i = 0; i < 2; i++) {
            float4 v = a_reg[i];
            *(uint4*)&As[a_row * AP + a_c0 + i * 4] =
                make_uint4(f2tf32(v.x), f2tf32(v.y), f2tf32(v.z), f2tf32(v.w));
            v = b_reg[i];
            *(uint4*)&Bs[b_k * BP + b_n0 + i * 64] =
                make_uint4(f2tf32(v.x), f2tf32(v.y), f2tf32(v.z), f2tf32(v.w));
        }
        __syncthreads();

        if (k0 + 16 < K) {
#pragma unroll
            for (int i = 0; i < 2; i++) {
                a_reg[i] = make_float4(0.f, 0.f, 0.f, 0.f);
                if (a_ok)
                    a_reg[i] = *(const float4*)(A + (size_t)(row0 + a_row) * K + k0 + 16 + a_c0 + i * 4);
                b_reg[i] = *(const float4*)(W + (size_t)(k0 + 16 + b_k) * F_H + col0 + b_n0 + i * 64);
            }
        }

#pragma unroll
        for (int kk = 0; kk < 16; kk += 8) {
            unsigned a[2][4];
#pragma unroll
            for (int t = 0; t < 2; t++) {
                int mr = wm + t * 16;
                a[t][0] = As[(mr + lg) * AP + kk + lt];
                a[t][1] = As[(mr + lg + 8) * AP + kk + lt];
                a[t][2] = As[(mr + lg) * AP + kk + lt + 4];
                a[t][3] = As[(mr + lg + 8) * AP + kk + lt + 4];
            }
#pragma unroll
            for (int j = 0; j < 8; j++) {
                unsigned b[2];
                int n = wn + j * 8 + lg;
                b[0] = Bs[(kk + lt) * BP + n];
                b[1] = Bs[(kk + lt + 4) * BP + n];
                mma_tf32(c[0][j], a[0], b);
                mma_tf32(c[1][j], a[1], b);
            }
        }
        __syncthreads();
    }

#pragma unroll
    for (int t = 0; t < 2; t++) {
        int r0 = row0 + wm + t * 16 + lg;
#pragma unroll
        for (int j = 0; j < 8; j++) {
            int cc = col0 + wn + j * 8 + lt * 2;
            if (r0 < Nn)
                *(float2*)(Cout + (size_t)r0 * F_H + cc) = make_float2(c[t][j][0], c[t][j][1]);
            if (r0 + 8 < Nn)
                *(float2*)(Cout + (size_t)(r0 + 8) * F_H + cc) = make_float2(c[t][j][2], c[t][j][3]);
        }
    }
}

// ---------------- alpha projections ----------------
__global__ void k_alpha(const float* __restrict__ a_src, const float* __restrict__ a_dst) {
    int idx = blockIdx.x * blockDim.x + threadIdx.x;
    if (idx >= Nn * NHEAD) return;
    int n = idx >> 3, h = idx & 7;
    const float4* hp = (const float4*)(g_h + (size_t)n * F_H + h * CCH);
    const float4* as = (const float4*)(a_src + h * CCH);
    const float4* ad = (const float4*)(a_dst + h * CCH);
    float s = 0.f, d = 0.f;
#pragma unroll
    for (int i = 0; i < 8; i++) {
        float4 v = hp[i], a = as[i], b = ad[i];
        s += v.x * a.x + v.y * a.y + v.z * a.z + v.w * a.w;
        d += v.x * b.x + v.y * b.y + v.z * b.z + v.w * b.w;
    }
    g_as[idx] = s;
    g_ad[idx] = d;
}

// ---------------- CSR build ----------------
__global__ void k_zero_count() {
    int i = blockIdx.x * blockDim.x + threadIdx.x;
    if (i < Nn) g_count[i] = 0;
}
__global__ void k_count(const int* __restrict__ ei, int E) {
    int e = blockIdx.x * blockDim.x + threadIdx.x;
    if (e < E) atomicAdd(&g_count[ei[E + e]], 1);
}
__global__ void __launch_bounds__(SCAN_T) k_scan(int E) {
    __shared__ int ssum[SCAN_T];
    int t = threadIdx.x;
    int base = t * CHUNK;
    int s = 0;
#pragma unroll
    for (int i = 0; i < CHUNK; i++) {
        int idx = base + i;
        if (idx < Nn) s += g_count[idx];
    }
    ssum[t] = s;
    __syncthreads();
    for (int off = 1; off < SCAN_T; off <<= 1) {
        int v = (t >= off) ? ssum[t - off] : 0;
        __syncthreads();
        ssum[t] += v;
        __syncthreads();
    }
    int run = ssum[t] - s;
#pragma unroll
    for (int i = 0; i < CHUNK; i++) {
        int idx = base + i;
        if (idx < Nn) {
            int c = g_count[idx];
            g_rowptr[idx] = run;
            g_cursor[idx] = run;
            run += c;
        }
    }
    if (t == 0) g_rowptr[Nn] = E;
}
__global__ void k_scatter2(const int* __restrict__ ei, int E) {
    int e = blockIdx.x * blockDim.x + threadIdx.x;
    if (e >= E) return;
    int dst = ei[E + e];
    int pos = atomicAdd(&g_cursor[dst], 1);
    g_csrc[pos] = ei[e];
    g_cdst[pos] = dst;
}

// ---------------- zero agg ----------------
__global__ void k_zero_agg() {
    int i = blockIdx.x * blockDim.x + threadIdx.x;
    if (i < Nn * F_H) g_agg[i] = 0.f;
}

// ---------------- edge weights (head-major, CSR order) ----------------
__global__ void k_weights(int E) {
    int e = blockIdx.x * blockDim.x + threadIdx.x;
    if (e >= E) return;
    int src = g_csrc[e];
    int dst = g_cdst[e];
    float4 s0 = *(const float4*)(g_as + src * NHEAD);
    float4 s1 = *(const float4*)(g_as + src * NHEAD + 4);
    float4 d0 = *(const float4*)(g_ad + dst * NHEAD);
    float4 d1 = *(const float4*)(g_ad + dst * NHEAD + 4);
    g_wT[0 * (size_t)E + e] = __expf(leaky(s0.x + d0.x));
    g_wT[1 * (size_t)E + e] = __expf(leaky(s0.y + d0.y));
    g_wT[2 * (size_t)E + e] = __expf(leaky(s0.z + d0.z));
    g_wT[3 * (size_t)E + e] = __expf(leaky(s0.w + d0.w));
    g_wT[4 * (size_t)E + e] = __expf(leaky(s1.x + d1.x));
    g_wT[5 * (size_t)E + e] = __expf(leaky(s1.y + d1.y));
    g_wT[6 * (size_t)E + e] = __expf(leaky(s1.z + d1.z));
    g_wT[7 * (size_t)E + e] = __expf(leaky(s1.w + d1.w));
}

// ---------------- softmax denominators: contiguous row-sums of g_wT ----------------
__global__ void k_den(int E) {
    int idx = blockIdx.x * blockDim.x + threadIdx.x;
    if (idx >= Nn * NHEAD) return;
    int n = idx >> 3, h = idx & 7;
    int beg = g_rowptr[n], end = g_rowptr[n + 1];
    const float* wr = g_wT + (size_t)h * E;
    float a = 0.f, b = 0.f, c = 0.f, d = 0.f;
    int k = beg;
    for (; k + 4 <= end; k += 4) {
        a += wr[k]; b += wr[k + 1]; c += wr[k + 2]; d += wr[k + 3];
    }
    for (; k < end; k++) a += wr[k];
    g_den[idx] = (a + b) + (c + d);
}

// ---------------- CSR-ordered dedup push ----------------
// Group of 8 lanes handles 8 CSR positions. Lane j owns feature columns
// j*4 + i*32 (i = head). Lane j loads head-j weights coalesced; per-edge
// all-head weights are recovered via 8-wide shfl transpose. Consecutive
// positions mostly share dst -> accumulate in registers, RED only on
// segment boundaries.
__global__ void __launch_bounds__(256) k_edge_csr(int E) {
    int tid = blockIdx.x * blockDim.x + threadIdx.x;
    int g = tid >> 3, j = tid & 7;
    int base = g * 8;
    unsigned mask = __ballot_sync(0xFFFFFFFFu, base < E);
    if (base >= E) return;
    int cnt = min(8, E - base);

    int s[8], d[8];
    float wl[8];                       // head-j weight for each of the 8 edges
    if (cnt == 8) {
        int4 i0 = *(const int4*)&g_csrc[base], i1 = *(const int4*)&g_csrc[base + 4];
        s[0] = i0.x; s[1] = i0.y; s[2] = i0.z; s[3] = i0.w;
        s[4] = i1.x; s[5] = i1.y; s[6] = i1.z; s[7] = i1.w;
        int4 e0 = *(const int4*)&g_cdst[base], e1 = *(const int4*)&g_cdst[base + 4];
        d[0] = e0.x; d[1] = e0.y; d[2] = e0.z; d[3] = e0.w;
        d[4] = e1.x; d[5] = e1.y; d[6] = e1.z; d[7] = e1.w;
        const float* wr = g_wT + (size_t)j * E + base;
        float4 w0 = *(const float4*)wr, w1 = *(const float4*)(wr + 4);
        wl[0] = w0.x; wl[1] = w0.y; wl[2] = w0.z; wl[3] = w0.w;
        wl[4] = w1.x; wl[5] = w1.y; wl[6] = w1.z; wl[7] = w1.w;
    } else {
#pragma unroll
        for (int p = 0; p < 8; p++) {
            int q = (p < cnt) ? base + p : base + cnt - 1;
            s[p] = g_csrc[q];
            d[p] = g_cdst[q];
            wl[p] = (p < cnt) ? g_wT[(size_t)j * E + q] : 0.f;  // padded: adds zero
        }
    }

    float4 acc[8];
    int cur = d[0];
    {
        float wh[8];
#pragma unroll
        for (int i = 0; i < 8; i++) wh[i] = __shfl_sync(mask, wl[0], i, 8);
        const float4* hp = (const float4*)(g_h + (size_t)s[0] * F_H) + j;
#pragma unroll
        for (int i = 0; i < 8; i++) {
            float4 hv = __ldg(hp + i * 8);
            acc[i] = make_float4(wh[i] * hv.x, wh[i] * hv.y, wh[i] * hv.z, wh[i] * hv.w);
        }
    }
#pragma unroll
    for (int p = 1; p < 8; p++) {
        float wh[8];
#pragma unroll
        for (int i = 0; i < 8; i++) wh[i] = __shfl_sync(mask, wl[p], i, 8);
        const float4* hp = (const float4*)(g_h + (size_t)s[p] * F_H) + j;
        if (d[p] != cur) {
            float* op = g_agg + (size_t)cur * F_H + j * 4;
#pragma unroll
            for (int i = 0; i < 8; i++)
                red4(op + i * 32, acc[i].x, acc[i].y, acc[i].z, acc[i].w);
            cur = d[p];
#pragma unroll
            for (int i = 0; i < 8; i++) {
                float4 hv = __ldg(hp + i * 8);
                acc[i] = make_float4(wh[i] * hv.x, wh[i] * hv.y, wh[i] * hv.z, wh[i] * hv.w);
            }
        } else {
#pragma unroll
            for (int i = 0; i < 8; i++) {
                float4 hv = __ldg(hp + i * 8);
                acc[i].x += wh[i] * hv.x; acc[i].y += wh[i] * hv.y;
                acc[i].z += wh[i] * hv.z; acc[i].w += wh[i] * hv.w;
            }
        }
    }
    float* op = g_agg + (size_t)cur * F_H + j * 4;
#pragma unroll
    for (int i = 0; i < 8; i++)
        red4(op + i * 32, acc[i].x, acc[i].y, acc[i].z, acc[i].w);
}

// ---------------- epilogue layer 1 (self-loop fold, divide, bias, ELU; re-zero agg) ----
__global__ void k_elu1(const float* __restrict__ b) {
    int idx = blockIdx.x * blockDim.x + threadIdx.x;
    if (idx >= Nn * F_H) return;
    int n = idx >> 8, f = idx & 255, h = f >> 5;
    float ws = __expf(leaky(g_as[n * NHEAD + h] + g_ad[n * NHEAD + h]));
    float num = g_agg[idx] + ws * g_h[idx];
    float den = g_den[n * NHEAD + h] + ws;
    float v = num / den + b[f];
    g_x2[idx] = (v > 0.f) ? v : expm1f(v);
    g_agg[idx] = 0.f;
}

// ---------------- epilogue layer 2 + linear head ----------------
__global__ void k_final(const float* __restrict__ b2, const float* __restrict__ Wl,
                        const float* __restrict__ bl, float* __restrict__ out) {
    int gid = blockIdx.x * blockDim.x + threadIdx.x;
    int n = gid >> 5, lane = gid & 31;
    if (n >= Nn) return;
    float s = 0.f;
#pragma unroll
    for (int k = 0; k < 8; k++) {
        int f = lane + 32 * k;
        float ws = __expf(leaky(g_as[n * NHEAD + k] + g_ad[n * NHEAD + k]));
        float num = g_agg[(size_t)n * F_H + f] + ws * g_h[(size_t)n * F_H + f];
        float den = g_den[n * NHEAD + k] + ws;
        float v = num / den + b2[f];
        v = (v > 0.f) ? v : expm1f(v);
        s += v * Wl[f];
    }
#pragma unroll
    for (int o = 16; o > 0; o >>= 1) s += __shfl_down_sync(0xFFFFFFFFu, s, o);
    if (lane == 0) out[n] = s + bl[0];
}

// ---------------- host ----------------
extern "C" void kernel_launch(void* const* d_in, const int* in_sizes, int n_in,
                              void* d_out, int out_size) {
    const float* x   = (const float*)d_in[0];
    const int*   ei  = (const int*)  d_in[1];
    const float* W1  = (const float*)d_in[2];
    const float* a1s = (const float*)d_in[3];
    const float* a1d = (const float*)d_in[4];
    const float* b1  = (const float*)d_in[5];
    const float* W2  = (const float*)d_in[6];
    const float* a2s = (const float*)d_in[7];
    const float* a2d = (const float*)d_in[8];
    const float* b2  = (const float*)d_in[9];
    const float* Wl  = (const float*)d_in[10];
    const float* bl  = (const float*)d_in[11];
    float* out = (float*)d_out;

    const int E = in_sizes[1] / 2;          // 480000

    float* g_h_p;  cudaGetSymbolAddress((void**)&g_h_p,  g_h);
    float* g_x2_p; cudaGetSymbolAddress((void**)&g_x2_p, g_x2);

    const int T = 256;
    dim3 gemm_grid(F_H / 128, (Nn + 127) / 128);
    int nh_blocks = (Nn * NHEAD + T - 1) / T;
    int e_blocks  = (E + T - 1) / T;
    int nf_blocks = (Nn * F_H + T - 1) / T;
    int fin_blocks = (Nn * 32 + T - 1) / T;

    // ---------- CSR build + zero agg (shared by both layers) ----------
    k_zero_agg<<<nf_blocks, T>>>();
    k_zero_count<<<(Nn + T - 1) / T, T>>>();
    k_count<<<e_blocks, T>>>(ei, E);
    k_scan<<<1, SCAN_T>>>(E);
    k_scatter2<<<e_blocks, T>>>(ei, E);

    // ---------- layer 1 ----------
    k_gemm_tf32<F_IN><<<gemm_grid, T>>>(x, W1, g_h_p);
    k_alpha<<<nh_blocks, T>>>(a1s, a1d);
    k_weights<<<e_blocks, T>>>(E);
    k_den<<<nh_blocks, T>>>(E);
    k_edge_csr<<<e_blocks, T>>>(E);
    k_elu1<<<nf_blocks, T>>>(b1);

    // ---------- layer 2 ----------
    k_gemm_tf32<F_H><<<gemm_grid, T>>>(g_x2_p, W2, g_h_p);
    k_alpha<<<nh_blocks, T>>>(a2s, a2d);
    k_weights<<<e_blocks, T>>>(E);
    k_den<<<nh_blocks, T>>>(E);
    k_edge_csr<<<e_blocks, T>>>(E);
    k_final<<<fin_blocks, T>>>(b2, Wl, bl, out);
}

// round 10
// speedup vs baseline: 1.1760x; 1.1089x over previous
#include <cuda_runtime.h>
#include <cstdint>

// ---------------- problem constants ----------------
#define Nn     30000
#define F_IN   128
#define F_H    256
#define NHEAD  8
#define CCH    32
#define NEG_SLOPE 0.2f
#define EMAX   480000
#define SBLK   30          // scan blocks
#define SCHUNK 1000        // elements per scan block (30*1000 = 30000)

// ---------------- device scratch (no allocs allowed) ----------------
__device__ float g_h  [(size_t)Nn * F_H];
__device__ float g_agg[(size_t)Nn * F_H];
__device__ float g_x2 [(size_t)Nn * F_H];
__device__ float g_as [(size_t)Nn * NHEAD];
__device__ float g_ad [(size_t)Nn * NHEAD];
__device__ float g_den[(size_t)Nn * NHEAD];
__device__ float g_wT [(size_t)NHEAD * EMAX];   // head-major edge weights, CSR order
__device__ int   g_count [Nn];
__device__ int   g_rowptr[Nn + 1];
__device__ int   g_cursor[Nn];
__device__ int   g_bsum  [SBLK];
__device__ int   g_boff  [SBLK];
__device__ int2  g_cpair [EMAX + 1024];         // (src,dst) per CSR position

__device__ __forceinline__ void red4(float* p, float a, float b, float c, float d) {
    asm volatile("red.global.add.v4.f32 [%0], {%1,%2,%3,%4};"
                 :: "l"(p), "f"(a), "f"(b), "f"(c), "f"(d) : "memory");
}
__device__ __forceinline__ float leaky(float v) {
    return (v > 0.f) ? v : NEG_SLOPE * v;
}
__device__ __forceinline__ unsigned f2tf32(float f) {
    unsigned u;
    asm("cvt.rna.tf32.f32 %0, %1;" : "=r"(u) : "f"(f));
    return u;
}
__device__ __forceinline__ void mma_tf32(float c[4], const unsigned a[4], const unsigned b[2]) {
    asm volatile(
        "mma.sync.aligned.m16n8k8.row.col.f32.tf32.tf32.f32 "
        "{%0,%1,%2,%3}, {%4,%5,%6,%7}, {%8,%9}, {%0,%1,%2,%3};"
        : "+f"(c[0]), "+f"(c[1]), "+f"(c[2]), "+f"(c[3])
        : "r"(a[0]), "r"(a[1]), "r"(a[2]), "r"(a[3]), "r"(b[0]), "r"(b[1]));
}

// ---------------- tf32 MMA GEMM with register double-buffering ----------------
#define AP 20
#define BP 136

template <int K>
__global__ void __launch_bounds__(256) k_gemm_tf32(const float* __restrict__ A,
                                                   const float* __restrict__ W,
                                                   float* __restrict__ Cout) {
    __shared__ unsigned As[128 * AP];
    __shared__ unsigned Bs[16 * BP];

    const int tid    = threadIdx.x;
    const int lane   = tid & 31;
    const int warpid = tid >> 5;
    const int row0   = blockIdx.y * 128;
    const int col0   = blockIdx.x * 128;
    const int wm     = (warpid & 3) * 32;
    const int wn     = (warpid >> 2) * 64;
    const int lg     = lane >> 2;
    const int lt     = lane & 3;

    float c[2][8][4];
#pragma unroll
    for (int t = 0; t < 2; t++)
#pragma unroll
        for (int j = 0; j < 8; j++)
#pragma unroll
            for (int r = 0; r < 4; r++) c[t][j][r] = 0.f;

    const int  a_row = tid >> 1;
    const int  a_c0  = (tid & 1) * 8;
    const int  b_k   = tid >> 4;
    const int  b_n0  = (tid & 15) * 4;
    const bool a_ok  = (row0 + a_row) < Nn;

    float4 a_reg[2], b_reg[2];
#pragma unroll
    for (int i = 0; i < 2; i++) {
        a_reg[i] = make_float4(0.f, 0.f, 0.f, 0.f);
        if (a_ok)
            a_reg[i] = *(const float4*)(A + (size_t)(row0 + a_row) * K + a_c0 + i * 4);
        b_reg[i] = *(const float4*)(W + (size_t)b_k * F_H + col0 + b_n0 + i * 64);
    }

    for (int k0 = 0; k0 < K; k0 += 16) {
#pragma unroll
        for (int i = 0; i < 2; i++) {
            float4 v = a_reg[i];
            *(uint4*)&As[a_row * AP + a_c0 + i * 4] =
                make_uint4(f2tf32(v.x), f2tf32(v.y), f2tf32(v.z), f2tf32(v.w));
            v = b_reg[i];
            *(uint4*)&Bs[b_k * BP + b_n0 + i * 64] =
                make_uint4(f2tf32(v.x), f2tf32(v.y), f2tf32(v.z), f2tf32(v.w));
        }
        __syncthreads();

        if (k0 + 16 < K) {
#pragma unroll
            for (int i = 0; i < 2; i++) {
                a_reg[i] = make_float4(0.f, 0.f, 0.f, 0.f);
                if (a_ok)
                    a_reg[i] = *(const float4*)(A + (size_t)(row0 + a_row) * K + k0 + 16 + a_c0 + i * 4);
                b_reg[i] = *(const float4*)(W + (size_t)(k0 + 16 + b_k) * F_H + col0 + b_n0 + i * 64);
            }
        }

#pragma unroll
        for (int kk = 0; kk < 16; kk += 8) {
            unsigned a[2][4];
#pragma unroll
            for (int t = 0; t < 2; t++) {
                int mr = wm + t * 16;
                a[t][0] = As[(mr + lg) * AP + kk + lt];
                a[t][1] = As[(mr + lg + 8) * AP + kk + lt];
                a[t][2] = As[(mr + lg) * AP + kk + lt + 4];
                a[t][3] = As[(mr + lg + 8) * AP + kk + lt + 4];
            }
#pragma unroll
            for (int j = 0; j < 8; j++) {
                unsigned b[2];
                int n = wn + j * 8 + lg;
                b[0] = Bs[(kk + lt) * BP + n];
                b[1] = Bs[(kk + lt + 4) * BP + n];
                mma_tf32(c[0][j], a[0], b);
                mma_tf32(c[1][j], a[1], b);
            }
        }
        __syncthreads();
    }

#pragma unroll
    for (int t = 0; t < 2; t++) {
        int r0 = row0 + wm + t * 16 + lg;
#pragma unroll
        for (int j = 0; j < 8; j++) {
            int cc = col0 + wn + j * 8 + lt * 2;
            if (r0 < Nn)
                *(float2*)(Cout + (size_t)r0 * F_H + cc) = make_float2(c[t][j][0], c[t][j][1]);
            if (r0 + 8 < Nn)
                *(float2*)(Cout + (size_t)(r0 + 8) * F_H + cc) = make_float2(c[t][j][2], c[t][j][3]);
        }
    }
}

// ---------------- alpha projections ----------------
__global__ void k_alpha(const float* __restrict__ a_src, const float* __restrict__ a_dst) {
    int idx = blockIdx.x * blockDim.x + threadIdx.x;
    if (idx >= Nn * NHEAD) return;
    int n = idx >> 3, h = idx & 7;
    const float4* hp = (const float4*)(g_h + (size_t)n * F_H + h * CCH);
    const float4* as = (const float4*)(a_src + h * CCH);
    const float4* ad = (const float4*)(a_dst + h * CCH);
    float s = 0.f, d = 0.f;
#pragma unroll
    for (int i = 0; i < 8; i++) {
        float4 v = hp[i], a = as[i], b = ad[i];
        s += v.x * a.x + v.y * a.y + v.z * a.z + v.w * a.w;
        d += v.x * b.x + v.y * b.y + v.z * b.z + v.w * b.w;
    }
    g_as[idx] = s;
    g_ad[idx] = d;
}

// ---------------- CSR build ----------------
__global__ void k_zero_count() {
    int i = blockIdx.x * blockDim.x + threadIdx.x;
    if (i < Nn) g_count[i] = 0;
}
__global__ void k_count(const int* __restrict__ ei, int E) {
    int e = blockIdx.x * blockDim.x + threadIdx.x;
    if (e < E) atomicAdd(&g_count[ei[E + e]], 1);
}
// phase 1: per-block chunk sums (coalesced)
__global__ void __launch_bounds__(1024) k_scan1() {
    __shared__ int red[32];
    int b = blockIdx.x, t = threadIdx.x;
    int v = (t < SCHUNK) ? g_count[b * SCHUNK + t] : 0;
#pragma unroll
    for (int o = 16; o > 0; o >>= 1) v += __shfl_down_sync(0xFFFFFFFFu, v, o);
    if ((t & 31) == 0) red[t >> 5] = v;
    __syncthreads();
    if (t < 32) {
        int s = red[t];
#pragma unroll
        for (int o = 16; o > 0; o >>= 1) s += __shfl_down_sync(0xFFFFFFFFu, s, o);
        if (t == 0) g_bsum[b] = s;
    }
}
// phase 2: exclusive scan of 30 block sums (1 warp)
__global__ void k_scan2() {
    int t = threadIdx.x;
    int v = (t < SBLK) ? g_bsum[t] : 0;
    int incl = v;
#pragma unroll
    for (int o = 1; o < 32; o <<= 1) {
        int u = __shfl_up_sync(0xFFFFFFFFu, incl, o);
        if (t >= o) incl += u;
    }
    if (t < SBLK) g_boff[t] = incl - v;
}
// phase 3: per-chunk exclusive scan + offsets; write rowptr/cursor (coalesced)
__global__ void __launch_bounds__(1024) k_scan3(int E) {
    __shared__ int sv[1024];
    int b = blockIdx.x, t = threadIdx.x;
    int c = (t < SCHUNK) ? g_count[b * SCHUNK + t] : 0;
    sv[t] = c;
    __syncthreads();
    for (int o = 1; o < 1024; o <<= 1) {
        int u = (t >= o) ? sv[t - o] : 0;
        __syncthreads();
        sv[t] += u;
        __syncthreads();
    }
    if (t < SCHUNK) {
        int excl = sv[t] - c + g_boff[b];
        g_rowptr[b * SCHUNK + t] = excl;
        g_cursor[b * SCHUNK + t] = excl;
    }
    if (b == SBLK - 1 && t == 0) g_rowptr[Nn] = E;
}
__global__ void k_scatter2(const int* __restrict__ ei, int E) {
    int e = blockIdx.x * blockDim.x + threadIdx.x;
    if (e >= E) return;
    int src = ei[e];
    int dst = ei[E + e];
    int pos = atomicAdd(&g_cursor[dst], 1);
    g_cpair[pos] = make_int2(src, dst);
}

// ---------------- zero agg ----------------
__global__ void k_zero_agg() {
    int i = blockIdx.x * blockDim.x + threadIdx.x;
    if (i < Nn * F_H) g_agg[i] = 0.f;
}

// ---------------- edge weights (head-major, CSR order) ----------------
__global__ void k_weights(int E) {
    int e = blockIdx.x * blockDim.x + threadIdx.x;
    if (e >= E) return;
    int2 p = g_cpair[e];
    float4 s0 = *(const float4*)(g_as + p.x * NHEAD);
    float4 s1 = *(const float4*)(g_as + p.x * NHEAD + 4);
    float4 d0 = *(const float4*)(g_ad + p.y * NHEAD);
    float4 d1 = *(const float4*)(g_ad + p.y * NHEAD + 4);
    g_wT[0 * (size_t)E + e] = __expf(leaky(s0.x + d0.x));
    g_wT[1 * (size_t)E + e] = __expf(leaky(s0.y + d0.y));
    g_wT[2 * (size_t)E + e] = __expf(leaky(s0.z + d0.z));
    g_wT[3 * (size_t)E + e] = __expf(leaky(s0.w + d0.w));
    g_wT[4 * (size_t)E + e] = __expf(leaky(s1.x + d1.x));
    g_wT[5 * (size_t)E + e] = __expf(leaky(s1.y + d1.y));
    g_wT[6 * (size_t)E + e] = __expf(leaky(s1.z + d1.z));
    g_wT[7 * (size_t)E + e] = __expf(leaky(s1.w + d1.w));
}

// ---------------- softmax denominators: contiguous row-sums of g_wT ----------------
__global__ void k_den(int E) {
    int idx = blockIdx.x * blockDim.x + threadIdx.x;
    if (idx >= Nn * NHEAD) return;
    int n = idx >> 3, h = idx & 7;
    int beg = g_rowptr[n], end = g_rowptr[n + 1];
    const float* wr = g_wT + (size_t)h * E;
    float a = 0.f, b = 0.f, c = 0.f, d = 0.f;
    int k = beg;
    for (; k + 4 <= end; k += 4) {
        a += wr[k]; b += wr[k + 1]; c += wr[k + 2]; d += wr[k + 3];
    }
    for (; k < end; k++) a += wr[k];
    g_den[idx] = (a + b) + (c + d);
}

// ---------------- CSR-ordered dedup push ----------------
__global__ void __launch_bounds__(256) k_edge_csr(int E) {
    int tid = blockIdx.x * blockDim.x + threadIdx.x;
    int g = tid >> 3, j = tid & 7;
    int base = g * 8;
    unsigned mask = __ballot_sync(0xFFFFFFFFu, base < E);
    if (base >= E) return;
    int cnt = min(8, E - base);

    int s[8], d[8];
    float wl[8];                       // head-j weight for each of the 8 edges
    if (cnt == 8) {
        const int4* pp = (const int4*)&g_cpair[base];   // 2 edges per int4
#pragma unroll
        for (int q = 0; q < 4; q++) {
            int4 pr = pp[q];
            s[q * 2] = pr.x; d[q * 2] = pr.y;
            s[q * 2 + 1] = pr.z; d[q * 2 + 1] = pr.w;
        }
        const float* wr = g_wT + (size_t)j * E + base;
        float4 w0 = *(const float4*)wr, w1 = *(const float4*)(wr + 4);
        wl[0] = w0.x; wl[1] = w0.y; wl[2] = w0.z; wl[3] = w0.w;
        wl[4] = w1.x; wl[5] = w1.y; wl[6] = w1.z; wl[7] = w1.w;
    } else {
#pragma unroll
        for (int p = 0; p < 8; p++) {
            int q = (p < cnt) ? base + p : base + cnt - 1;
            int2 pr = g_cpair[q];
            s[p] = pr.x;
            d[p] = pr.y;
            wl[p] = (p < cnt) ? g_wT[(size_t)j * E + q] : 0.f;  // padded: adds zero
        }
    }

    float4 acc[8];
    int cur = d[0];
    {
        float wh[8];
#pragma unroll
        for (int i = 0; i < 8; i++) wh[i] = __shfl_sync(mask, wl[0], i, 8);
        const float4* hp = (const float4*)(g_h + (size_t)s[0] * F_H) + j;
#pragma unroll
        for (int i = 0; i < 8; i++) {
            float4 hv = __ldg(hp + i * 8);
            acc[i] = make_float4(wh[i] * hv.x, wh[i] * hv.y, wh[i] * hv.z, wh[i] * hv.w);
        }
    }
#pragma unroll
    for (int p = 1; p < 8; p++) {
        float wh[8];
#pragma unroll
        for (int i = 0; i < 8; i++) wh[i] = __shfl_sync(mask, wl[p], i, 8);
        const float4* hp = (const float4*)(g_h + (size_t)s[p] * F_H) + j;
        if (d[p] != cur) {
            float* op = g_agg + (size_t)cur * F_H + j * 4;
#pragma unroll
            for (int i = 0; i < 8; i++)
                red4(op + i * 32, acc[i].x, acc[i].y, acc[i].z, acc[i].w);
            cur = d[p];
#pragma unroll
            for (int i = 0; i < 8; i++) {
                float4 hv = __ldg(hp + i * 8);
                acc[i] = make_float4(wh[i] * hv.x, wh[i] * hv.y, wh[i] * hv.z, wh[i] * hv.w);
            }
        } else {
#pragma unroll
            for (int i = 0; i < 8; i++) {
                float4 hv = __ldg(hp + i * 8);
                acc[i].x += wh[i] * hv.x; acc[i].y += wh[i] * hv.y;
                acc[i].z += wh[i] * hv.z; acc[i].w += wh[i] * hv.w;
            }
        }
    }
    float* op = g_agg + (size_t)cur * F_H + j * 4;
#pragma unroll
    for (int i = 0; i < 8; i++)
        red4(op + i * 32, acc[i].x, acc[i].y, acc[i].z, acc[i].w);
}

// ---------------- epilogue layer 1 (self-loop fold, divide, bias, ELU; re-zero agg) ----
__global__ void k_elu1(const float* __restrict__ b) {
    int idx = blockIdx.x * blockDim.x + threadIdx.x;
    if (idx >= Nn * F_H) return;
    int n = idx >> 8, f = idx & 255, h = f >> 5;
    float ws = __expf(leaky(g_as[n * NHEAD + h] + g_ad[n * NHEAD + h]));
    float num = g_agg[idx] + ws * g_h[idx];
    float den = g_den[n * NHEAD + h] + ws;
    float v = num / den + b[f];
    g_x2[idx] = (v > 0.f) ? v : expm1f(v);
    g_agg[idx] = 0.f;
}

// ---------------- epilogue layer 2 + linear head ----------------
__global__ void k_final(const float* __restrict__ b2, const float* __restrict__ Wl,
                        const float* __restrict__ bl, float* __restrict__ out) {
    int gid = blockIdx.x * blockDim.x + threadIdx.x;
    int n = gid >> 5, lane = gid & 31;
    if (n >= Nn) return;
    float s = 0.f;
#pragma unroll
    for (int k = 0; k < 8; k++) {
        int f = lane + 32 * k;
        float ws = __expf(leaky(g_as[n * NHEAD + k] + g_ad[n * NHEAD + k]));
        float num = g_agg[(size_t)n * F_H + f] + ws * g_h[(size_t)n * F_H + f];
        float den = g_den[n * NHEAD + k] + ws;
        float v = num / den + b2[f];
        v = (v > 0.f) ? v : expm1f(v);
        s += v * Wl[f];
    }
#pragma unroll
    for (int o = 16; o > 0; o >>= 1) s += __shfl_down_sync(0xFFFFFFFFu, s, o);
    if (lane == 0) out[n] = s + bl[0];
}

// ---------------- host ----------------
extern "C" void kernel_launch(void* const* d_in, const int* in_sizes, int n_in,
                              void* d_out, int out_size) {
    const float* x   = (const float*)d_in[0];
    const int*   ei  = (const int*)  d_in[1];
    const float* W1  = (const float*)d_in[2];
    const float* a1s = (const float*)d_in[3];
    const float* a1d = (const float*)d_in[4];
    const float* b1  = (const float*)d_in[5];
    const float* W2  = (const float*)d_in[6];
    const float* a2s = (const float*)d_in[7];
    const float* a2d = (const float*)d_in[8];
    const float* b2  = (const float*)d_in[9];
    const float* Wl  = (const float*)d_in[10];
    const float* bl  = (const float*)d_in[11];
    float* out = (float*)d_out;

    const int E = in_sizes[1] / 2;          // 480000

    float* g_h_p;  cudaGetSymbolAddress((void**)&g_h_p,  g_h);
    float* g_x2_p; cudaGetSymbolAddress((void**)&g_x2_p, g_x2);

    const int T = 256;
    dim3 gemm_grid(F_H / 128, (Nn + 127) / 128);
    int nh_blocks = (Nn * NHEAD + T - 1) / T;
    int e_blocks  = (E + T - 1) / T;
    int nf_blocks = (Nn * F_H + T - 1) / T;
    int fin_blocks = (Nn * 32 + T - 1) / T;

    // ---------- CSR build + zero agg (shared by both layers) ----------
    k_zero_agg<<<nf_blocks, T>>>();
    k_zero_count<<<(Nn + T - 1) / T, T>>>();
    k_count<<<e_blocks, T>>>(ei, E);
    k_scan1<<<SBLK, 1024>>>();
    k_scan2<<<1, 32>>>();
    k_scan3<<<SBLK, 1024>>>(E);
    k_scatter2<<<e_blocks, T>>>(ei, E);

    // ---------- layer 1 ----------
    k_gemm_tf32<F_IN><<<gemm_grid, T>>>(x, W1, g_h_p);
    k_alpha<<<nh_blocks, T>>>(a1s, a1d);
    k_weights<<<e_blocks, T>>>(E);
    k_den<<<nh_blocks, T>>>(E);
    k_edge_csr<<<e_blocks, T>>>(E);
    k_elu1<<<nf_blocks, T>>>(b1);

    // ---------- layer 2 ----------
    k_gemm_tf32<F_H><<<gemm_grid, T>>>(g_x2_p, W2, g_h_p);
    k_alpha<<<nh_blocks, T>>>(a2s, a2d);
    k_weights<<<e_blocks, T>>>(E);
    k_den<<<nh_blocks, T>>>(E);
    k_edge_csr<<<e_blocks, T>>>(E);
    k_final<<<fin_blocks, T>>>(b2, Wl, bl, out);
}